// round 13
// baseline (speedup 1.0000x reference)
#include <cuda_runtime.h>
#include <cuda_bf16.h>
#include <cuda_fp16.h>
#include <cstdint>

#define EPS 1e-5f
typedef __nv_bfloat16 bf16;

// ================= scratch (no allocation allowed) =================
__device__ bf16  g_qin_hi [8192L * 512];
__device__ bf16  g_qin_lo [8192L * 512];
__device__ bf16  g_kvin_hi[8192L * 512];
__device__ bf16  g_kvin_lo[8192L * 512];
__device__ bf16  g_inw_hi [1536L * 512];
__device__ bf16  g_inw_lo [1536L * 512];
__device__ bf16  g_outw_hi[512L * 512];
__device__ bf16  g_outw_lo[512L * 512];
__device__ bf16  g_ffw_hi [512L * 512];
__device__ bf16  g_ffw_lo [512L * 512];
__device__ bf16  g_q_hi   [8192L * 512];
__device__ bf16  g_q_lo   [8192L * 512];
__device__ float g_v      [8192L * 512];
__device__ bf16  g_k_hi   [8192L * 512];
__device__ bf16  g_k_lo   [8192L * 512];
__device__ bf16  g_vt_hi  [8L * 512 * 1024];
__device__ bf16  g_vt_lo  [8L * 512 * 1024];
__device__ __half g_p     [64LL * 1024 * 1024];   // unnormalized exp, fp16, 128 MB
__device__ float g_m      [64L * 8 * 1024];       // m used per (z, tile128, qrow)
__device__ float2 g_ml    [64L * 1024];           // final (m, l) per (z, qrow)
__device__ float g_c      [64L * 8 * 1024];       // corr = exp(m_used-m)/l
__device__ bf16  g_ctx_hi [8192L * 512];
__device__ bf16  g_ctx_lo [8192L * 512];
__device__ float g_x      [8192L * 512];
__device__ float g_xn     [8192L * 512];
__device__ bf16  g_xn_hi  [8192L * 512];
__device__ bf16  g_xn_lo  [8192L * 512];
__device__ float g_ff     [8192L * 512];

// ================= helpers =================
__device__ __forceinline__ uint32_t smem_u32(const void* p){
    uint32_t a;
    asm("{ .reg .u64 t; cvta.to.shared.u64 t, %1; cvt.u32.u64 %0, t; }" : "=r"(a) : "l"(p));
    return a;
}
#define CP_ASYNC16(dst, src) \
    asm volatile("cp.async.cg.shared.global [%0], [%1], 16;" :: "r"(dst), "l"(src))
#define CP_COMMIT() asm volatile("cp.async.commit_group;" ::: "memory")
#define CP_WAIT(n)  asm volatile("cp.async.wait_group %0;" :: "n"(n) : "memory")

__device__ __forceinline__ void ldsm4(uint32_t addr, uint32_t& r0, uint32_t& r1,
                                      uint32_t& r2, uint32_t& r3){
    asm volatile("ldmatrix.sync.aligned.m8n8.x4.shared.b16 {%0,%1,%2,%3}, [%4];"
                 : "=r"(r0), "=r"(r1), "=r"(r2), "=r"(r3) : "r"(addr));
}
__device__ __forceinline__ void mma16816(float* d, const uint32_t* a, const uint32_t* b){
    asm volatile("mma.sync.aligned.m16n8k16.row.col.f32.bf16.bf16.f32 "
                 "{%0,%1,%2,%3},{%4,%5,%6,%7},{%8,%9},{%0,%1,%2,%3};"
                 : "+f"(d[0]), "+f"(d[1]), "+f"(d[2]), "+f"(d[3])
                 : "r"(a[0]), "r"(a[1]), "r"(a[2]), "r"(a[3]), "r"(b[0]), "r"(b[1]));
}
__device__ __forceinline__ void split1(float v, bf16& h, bf16& l){
    h = __float2bfloat16_rn(v);
    l = __float2bfloat16_rn(v - __bfloat162float(h));
}
__device__ __forceinline__ uint32_t pack_bf2(bf16 a, bf16 b){
    return (uint32_t)__bfloat16_as_ushort(a) | ((uint32_t)__bfloat16_as_ushort(b) << 16);
}

// ================= shared GEMM mainloop =================
struct GemmOut {
    float* C; bf16 *Chi, *Clo;
    const float* bias; const float* resid;
    float scale;
};

__device__ __forceinline__ void gemm_core(
    const bf16* Ah, const bf16* Al, long lda,
    const bf16* Bh, const bf16* Bl, long ldb,
    int K, char* smem, int tid, float* acc /*2*8*4*/)
{
    constexpr int ROWB = 80;
    constexpr int ASZ = 128 * ROWB;
    constexpr int BSZ = 128 * ROWB;
    constexpr int STAGE = 2 * ASZ + 2 * BSZ;
    const int wid = tid >> 5, lane = tid & 31;
    const int wm = (wid & 3) * 32, wn = (wid >> 2) * 64;
    const uint32_t sb = smem_u32(smem);

    auto loadc = [&](int kc, int s){
        long k0 = (long)kc * 32;
        uint32_t base = sb + s * STAGE;
        #pragma unroll
        for (int i = 0; i < 2; i++) {
            int id = tid + i * 256; int r = id >> 2, c = id & 3;
            CP_ASYNC16(base + r * ROWB + c * 16,       Ah + (long)r * lda + k0 + c * 8);
            CP_ASYNC16(base + ASZ + r * ROWB + c * 16, Al + (long)r * lda + k0 + c * 8);
            CP_ASYNC16(base + 2*ASZ + r * ROWB + c * 16,       Bh + (long)r * ldb + k0 + c * 8);
            CP_ASYNC16(base + 2*ASZ + BSZ + r * ROWB + c * 16, Bl + (long)r * ldb + k0 + c * 8);
        }
        CP_COMMIT();
    };

    const int arow = (lane & 7) + ((lane & 8)  ? 8 : 0);
    const int acol = (lane & 16) ? 8 : 0;
    const int brow = (lane & 7) + ((lane & 16) ? 8 : 0);
    const int bcol = (lane & 8) ? 8 : 0;

    const int KC = K >> 5;
    loadc(0, 0);
    for (int kc = 0; kc < KC; kc++) {
        int s = kc & 1;
        if (kc + 1 < KC) { loadc(kc + 1, s ^ 1); CP_WAIT(1); }
        else             { CP_WAIT(0); }
        __syncthreads();
        uint32_t base = sb + s * STAGE;
        #pragma unroll
        for (int ph = 0; ph < 3; ph++) {
            uint32_t abuf = base + ((ph == 1) ? ASZ : 0);
            uint32_t bbuf = base + 2*ASZ + ((ph == 2) ? BSZ : 0);
            #pragma unroll
            for (int k16 = 0; k16 < 2; k16++) {
                uint32_t af[2][4];
                #pragma unroll
                for (int mi = 0; mi < 2; mi++)
                    ldsm4(abuf + (wm + mi * 16 + arow) * ROWB + (k16 * 16 + acol) * 2,
                          af[mi][0], af[mi][1], af[mi][2], af[mi][3]);
                uint32_t bfr[4][4];
                #pragma unroll
                for (int n2 = 0; n2 < 4; n2++)
                    ldsm4(bbuf + (wn + n2 * 16 + brow) * ROWB + (k16 * 16 + bcol) * 2,
                          bfr[n2][0], bfr[n2][1], bfr[n2][2], bfr[n2][3]);
                #pragma unroll
                for (int mi = 0; mi < 2; mi++)
                    #pragma unroll
                    for (int ni = 0; ni < 8; ni++)
                        mma16816(acc + (mi * 8 + ni) * 4, af[mi], bfr[ni >> 1] + (ni & 1) * 2);
            }
        }
        __syncthreads();
    }
}

__device__ __forceinline__ void gemm_epi(
    const float* acc, long bm, long bn, long ldc, long cbase,
    const GemmOut& o, int tid)
{
    const int wid = tid >> 5, lane = tid & 31;
    const int wm = (wid & 3) * 32, wn = (wid >> 2) * 64;
    #pragma unroll
    for (int mi = 0; mi < 2; mi++) {
        #pragma unroll
        for (int ni = 0; ni < 8; ni++) {
            const float* a4 = acc + (mi * 8 + ni) * 4;
            int n0 = (int)bn + wn + ni * 8 + (lane & 3) * 2;
            #pragma unroll
            for (int half = 0; half < 2; half++) {
                long m = bm + wm + mi * 16 + (lane >> 2) + half * 8;
                float v0 = a4[half * 2 + 0];
                float v1 = a4[half * 2 + 1];
                if (o.bias) { v0 += o.bias[n0]; v1 += o.bias[n0 + 1]; }
                v0 *= o.scale; v1 *= o.scale;
                if (o.resid) {
                    float2 rr = *(const float2*)(o.resid + cbase + m * ldc + n0);
                    v0 += rr.x; v1 += rr.y;
                }
                if (o.C) {
                    float2 ov; ov.x = v0; ov.y = v1;
                    *(float2*)(o.C + cbase + m * ldc + n0) = ov;
                }
                if (o.Chi) {
                    bf16 h0, l0, h1, l1;
                    split1(v0, h0, l0); split1(v1, h1, l1);
                    *(uint32_t*)(o.Chi + cbase + m * ldc + n0) = pack_bf2(h0, h1);
                    *(uint32_t*)(o.Clo + cbase + m * ldc + n0) = pack_bf2(l0, l1);
                }
            }
        }
    }
}

// ================= fused q/k/v projections: grid.z selects which =================
__global__ void __launch_bounds__(256)
proj_qkv(const bf16* __restrict__ qinh, const bf16* __restrict__ qinl,
         const bf16* __restrict__ kvinh, const bf16* __restrict__ kvinl,
         const bf16* __restrict__ inwh, const bf16* __restrict__ inwl,
         const float* __restrict__ in_b,
         bf16* __restrict__ qh, bf16* __restrict__ ql,
         bf16* __restrict__ kh, bf16* __restrict__ kl,
         float* __restrict__ v)
{
    extern __shared__ char smem[];
    const int tid = threadIdx.x;
    const int z = blockIdx.z;
    long bm = (long)blockIdx.y * 128;
    long bn = (long)blockIdx.x * 128;

    const bf16 *Ah, *Al;
    GemmOut o{nullptr, nullptr, nullptr, nullptr, nullptr, 1.0f};
    if (z == 0) { Ah = qinh;  Al = qinl;  o.Chi = qh; o.Clo = ql; o.scale = 0.125f; o.bias = in_b; }
    else if (z == 1) { Ah = kvinh; Al = kvinl; o.Chi = kh; o.Clo = kl; o.bias = in_b + 512; }
    else { Ah = kvinh; Al = kvinl; o.C = v; o.bias = in_b + 1024; }
    const bf16* Bh = inwh + (long)z * 512 * 512 + bn * 512;
    const bf16* Bl = inwl + (long)z * 512 * 512 + bn * 512;

    float acc[64];
    #pragma unroll
    for (int i = 0; i < 64; i++) acc[i] = 0.f;
    gemm_core(Ah + bm * 512, Al + bm * 512, 512, Bh, Bl, 512, 512, smem, tid, acc);
    gemm_epi(acc, bm, bn, 512, 0, o, tid);
}

// ================= generic GEMM (out-proj / ff) =================
__global__ void __launch_bounds__(256)
gemm_pi(const bf16* __restrict__ Ahi, const bf16* __restrict__ Alo,
        const bf16* __restrict__ Bhi, const bf16* __restrict__ Blo,
        float* __restrict__ C, bf16* __restrict__ Chi, bf16* __restrict__ Clo,
        float scale, const float* __restrict__ bias, const float* __restrict__ resid)
{
    extern __shared__ char smem[];
    const int tid = threadIdx.x;
    long bm = (long)blockIdx.y * 128;
    long bn = (long)blockIdx.x * 128;
    float acc[64];
    #pragma unroll
    for (int i = 0; i < 64; i++) acc[i] = 0.f;
    gemm_core(Ahi + bm * 512, Alo + bm * 512, 512,
              Bhi + bn * 512, Blo + bn * 512, 512, 512, smem, tid, acc);
    GemmOut o{C, Chi, Clo, bias, resid, scale};
    gemm_epi(acc, bm, bn, 512, 0, o, tid);
}

// ================= single-pass flash attention (P out as fp16) =================
__global__ void __launch_bounds__(256)
attn_flash(const bf16* __restrict__ qhi, const bf16* __restrict__ qlo,
           const bf16* __restrict__ khi, const bf16* __restrict__ klo,
           const bf16* __restrict__ vhi, const bf16* __restrict__ vlo,
           __half* __restrict__ P, float* __restrict__ Mbuf,
           float2* __restrict__ MLbuf,
           bf16* __restrict__ ctxhi, bf16* __restrict__ ctxlo)
{
    constexpr int PITCH  = 144;
    constexpr int PLANE  = 128 * PITCH;
    constexpr int VPITCH = 272;
    constexpr int VPLANE = 64 * VPITCH;
    extern __shared__ char smem[];
    const uint32_t sb  = smem_u32(smem);
    const uint32_t sQH = sb;
    const uint32_t sQL = sb + PLANE;
    const uint32_t sK0 = sb + 2 * PLANE;
    const uint32_t sV0 = sb + 6 * PLANE;
    float* stm = (float*)(smem + 6 * PLANE + 4 * VPLANE);        // [2][128]
    float* stl = (float*)(smem + 6 * PLANE + 4 * VPLANE + 1024);

    const int tid = threadIdx.x, wid = tid >> 5, lane = tid & 31;
    const int wm = (wid & 3) * 32, wn = (wid >> 2) * 64;
    const int g = wid >> 2;
    const int z = blockIdx.z, b_ = z >> 3, h_ = z & 7;
    const long qrow0 = (long)b_ * 1024 + blockIdx.x * 128;
    const bf16* Qh = qhi + qrow0 * 512 + h_ * 64;
    const bf16* Ql = qlo + qrow0 * 512 + h_ * 64;
    const bf16* Kh = khi + (long)b_ * 1024 * 512 + h_ * 64;
    const bf16* Kl = klo + (long)b_ * 1024 * 512 + h_ * 64;
    const bf16* Vh = vhi + (long)b_ * 512 * 1024 + (long)h_ * 64 * 1024;
    const bf16* Vl = vlo + (long)b_ * 512 * 1024 + (long)h_ * 64 * 1024;
    __half* Pz = P + ((long)z << 20) + (long)blockIdx.x * 128 * 1024;
    bf16* Chb = ctxhi + qrow0 * 512 + h_ * 64;
    bf16* Clb = ctxlo + qrow0 * 512 + h_ * 64;

    #pragma unroll
    for (int i = 0; i < 4; i++) {
        int id = tid + i * 256; int r = id >> 3, c = id & 7;
        CP_ASYNC16(sQH + r * PITCH + c * 16, Qh + (long)r * 512 + c * 8);
        CP_ASYNC16(sQL + r * PITCH + c * 16, Ql + (long)r * 512 + c * 8);
    }
    auto loadK = [&](int kt, int s){
        uint32_t dh = sK0 + s * 2 * PLANE, dl = dh + PLANE;
        const bf16* sh = Kh + (long)kt * 128 * 512;
        const bf16* sl = Kl + (long)kt * 128 * 512;
        #pragma unroll
        for (int i = 0; i < 4; i++) {
            int id = tid + i * 256; int r = id >> 3, c = id & 7;
            CP_ASYNC16(dh + r * PITCH + c * 16, sh + (long)r * 512 + c * 8);
            CP_ASYNC16(dl + r * PITCH + c * 16, sl + (long)r * 512 + c * 8);
        }
    };
    auto loadV = [&](int kt, int s){
        uint32_t dh = sV0 + s * 2 * VPLANE, dl = dh + VPLANE;
        const bf16* sh = Vh + (long)kt * 128;
        const bf16* sl = Vl + (long)kt * 128;
        #pragma unroll
        for (int i = 0; i < 4; i++) {
            int id = tid + i * 256; int r = id >> 4, c = id & 15;
            CP_ASYNC16(dh + r * VPITCH + c * 16, sh + (long)r * 1024 + c * 8);
            CP_ASYNC16(dl + r * VPITCH + c * 16, sl + (long)r * 1024 + c * 8);
        }
    };
    loadK(0, 0); loadV(0, 0);
    CP_COMMIT();

    const int arow = (lane & 7) + ((lane & 8)  ? 8 : 0);
    const int acol = (lane & 16) ? 8 : 0;
    const int brow = (lane & 7) + ((lane & 16) ? 8 : 0);
    const int bcol = (lane & 8) ? 8 : 0;

    float m_t[4], l_t[4];
    #pragma unroll
    for (int i = 0; i < 4; i++) { m_t[i] = -1e30f; l_t[i] = 0.f; }

    float oac[64];
    #pragma unroll
    for (int i = 0; i < 64; i++) oac[i] = 0.f;

    float acc[64];

    for (int t = 0; t < 8; t++) {
        int s = t & 1;
        if (t + 1 < 8) {
            loadK(t + 1, s ^ 1); loadV(t + 1, s ^ 1);
            CP_COMMIT(); CP_WAIT(1);
        } else {
            CP_WAIT(0);
        }
        __syncthreads();

        #pragma unroll
        for (int i = 0; i < 64; i++) acc[i] = 0.f;
        uint32_t kbase = sK0 + s * 2 * PLANE;
        #pragma unroll
        for (int ph = 0; ph < 3; ph++) {
            uint32_t abuf = (ph == 1) ? sQL : sQH;
            uint32_t bbuf = kbase + ((ph == 2) ? PLANE : 0);
            #pragma unroll
            for (int k16 = 0; k16 < 4; k16++) {
                uint32_t af[2][4];
                #pragma unroll
                for (int mi = 0; mi < 2; mi++)
                    ldsm4(abuf + (wm + mi * 16 + arow) * PITCH + (k16 * 16 + acol) * 2,
                          af[mi][0], af[mi][1], af[mi][2], af[mi][3]);
                uint32_t bfr[4][4];
                #pragma unroll
                for (int n2 = 0; n2 < 4; n2++)
                    ldsm4(bbuf + (n2 * 16 + brow) * PITCH + (k16 * 16 + bcol) * 2 + wn * PITCH,
                          bfr[n2][0], bfr[n2][1], bfr[n2][2], bfr[n2][3]);
                #pragma unroll
                for (int mi = 0; mi < 2; mi++)
                    #pragma unroll
                    for (int ni = 0; ni < 8; ni++)
                        mma16816(acc + (mi * 8 + ni) * 4, af[mi], bfr[ni >> 1] + (ni & 1) * 2);
            }
        }

        float tmax[4];
        #pragma unroll
        for (int mi = 0; mi < 2; mi++)
            #pragma unroll
            for (int half = 0; half < 2; half++) {
                int idx = mi * 2 + half;
                float vm = -1e30f;
                #pragma unroll
                for (int ni = 0; ni < 8; ni++) {
                    const float* a2 = acc + (mi * 8 + ni) * 4 + half * 2;
                    vm = fmaxf(vm, fmaxf(a2[0], a2[1]));
                }
                vm = fmaxf(vm, __shfl_xor_sync(0xffffffffu, vm, 1));
                vm = fmaxf(vm, __shfl_xor_sync(0xffffffffu, vm, 2));
                tmax[idx] = vm;
            }
        if ((lane & 3) == 0) {
            #pragma unroll
            for (int mi = 0; mi < 2; mi++)
                #pragma unroll
                for (int half = 0; half < 2; half++) {
                    int row = wm + mi * 16 + half * 8 + (lane >> 2);
                    stm[g * 128 + row] = tmax[mi * 2 + half];
                }
        }
        __syncthreads();

        float alpha[4], mnew[4];
        #pragma unroll
        for (int mi = 0; mi < 2; mi++)
            #pragma unroll
            for (int half = 0; half < 2; half++) {
                int idx = mi * 2 + half;
                int row = wm + mi * 16 + half * 8 + (lane >> 2);
                float tm = fmaxf(stm[row], stm[128 + row]);
                float mn = fmaxf(m_t[idx], tm);
                alpha[idx] = __expf(m_t[idx] - mn);
                mnew[idx] = mn;
                m_t[idx] = mn;
            }
        if (g == 0 && (lane & 3) == 0) {
            #pragma unroll
            for (int mi = 0; mi < 2; mi++)
                #pragma unroll
                for (int half = 0; half < 2; half++) {
                    int row = wm + mi * 16 + half * 8 + (lane >> 2);
                    Mbuf[(((long)z * 8 + t) << 10) + blockIdx.x * 128 + row] = mnew[mi * 2 + half];
                }
        }

        #pragma unroll
        for (int mi = 0; mi < 2; mi++)
            #pragma unroll
            for (int ni = 0; ni < 8; ni++)
                #pragma unroll
                for (int half = 0; half < 2; half++) {
                    float* o2 = oac + (mi * 8 + ni) * 4 + half * 2;
                    float a = alpha[mi * 2 + half];
                    o2[0] *= a; o2[1] *= a;
                }

        #pragma unroll
        for (int mi = 0; mi < 2; mi++)
            #pragma unroll
            for (int half = 0; half < 2; half++) {
                int idx = mi * 2 + half;
                float sum = 0.f;
                #pragma unroll
                for (int ni = 0; ni < 8; ni++) {
                    float* a2 = acc + (mi * 8 + ni) * 4 + half * 2;
                    a2[0] = __expf(a2[0] - mnew[idx]);
                    a2[1] = __expf(a2[1] - mnew[idx]);
                    sum += a2[0] + a2[1];
                }
                l_t[idx] = l_t[idx] * alpha[idx] + sum;
            }
        // write P'' as fp16
        #pragma unroll
        for (int mi = 0; mi < 2; mi++)
            #pragma unroll
            for (int ni = 0; ni < 8; ni++)
                #pragma unroll
                for (int half = 0; half < 2; half++) {
                    int row = wm + mi * 16 + half * 8 + (lane >> 2);
                    int n0 = t * 128 + wn + ni * 8 + (lane & 3) * 2;
                    const float* a2 = acc + (mi * 8 + ni) * 4 + half * 2;
                    __half2 o2 = __floats2half2_rn(a2[0], a2[1]);
                    *(__half2*)(Pz + (long)row * 1024 + n0) = o2;
                }

        uint32_t vb = sV0 + s * 2 * VPLANE;
        #pragma unroll
        for (int j = 0; j < 4; j++) {
            uint32_t ah[2][4], al[2][4];
            #pragma unroll
            for (int mi = 0; mi < 2; mi++) {
                const float* t0 = acc + (mi * 8 + 2 * j) * 4;
                const float* t1 = acc + (mi * 8 + 2 * j + 1) * 4;
                #pragma unroll
                for (int r = 0; r < 2; r++) {
                    bf16 h0, l0, h1, l1;
                    split1(t0[r * 2 + 0], h0, l0);
                    split1(t0[r * 2 + 1], h1, l1);
                    ah[mi][r] = pack_bf2(h0, h1);
                    al[mi][r] = pack_bf2(l0, l1);
                    bf16 g0, m0, g1, m1;
                    split1(t1[r * 2 + 0], g0, m0);
                    split1(t1[r * 2 + 1], g1, m1);
                    ah[mi][2 + r] = pack_bf2(g0, g1);
                    al[mi][2 + r] = pack_bf2(m0, m1);
                }
            }
            uint32_t bfr[4][4];
            #pragma unroll
            for (int n2 = 0; n2 < 4; n2++)
                ldsm4(vb + (n2 * 16 + brow) * VPITCH + (wn + j * 16 + bcol) * 2,
                      bfr[n2][0], bfr[n2][1], bfr[n2][2], bfr[n2][3]);
            #pragma unroll
            for (int mi = 0; mi < 2; mi++)
                #pragma unroll
                for (int ni = 0; ni < 8; ni++) {
                    mma16816(oac + (mi * 8 + ni) * 4, ah[mi], bfr[ni >> 1] + (ni & 1) * 2);
                    mma16816(oac + (mi * 8 + ni) * 4, al[mi], bfr[ni >> 1] + (ni & 1) * 2);
                }
            #pragma unroll
            for (int n2 = 0; n2 < 4; n2++)
                ldsm4(vb + VPLANE + (n2 * 16 + brow) * VPITCH + (wn + j * 16 + bcol) * 2,
                      bfr[n2][0], bfr[n2][1], bfr[n2][2], bfr[n2][3]);
            #pragma unroll
            for (int mi = 0; mi < 2; mi++)
                #pragma unroll
                for (int ni = 0; ni < 8; ni++)
                    mma16816(oac + (mi * 8 + ni) * 4, ah[mi], bfr[ni >> 1] + (ni & 1) * 2);
        }
        __syncthreads();
    }

    #pragma unroll
    for (int idx = 0; idx < 4; idx++) {
        l_t[idx] += __shfl_xor_sync(0xffffffffu, l_t[idx], 1);
        l_t[idx] += __shfl_xor_sync(0xffffffffu, l_t[idx], 2);
    }
    if ((lane & 3) == 0) {
        #pragma unroll
        for (int mi = 0; mi < 2; mi++)
            #pragma unroll
            for (int half = 0; half < 2; half++) {
                int row = wm + mi * 16 + half * 8 + (lane >> 2);
                stl[g * 128 + row] = l_t[mi * 2 + half];
            }
    }
    __syncthreads();
    float invl[4];
    #pragma unroll
    for (int mi = 0; mi < 2; mi++)
        #pragma unroll
        for (int half = 0; half < 2; half++) {
            int idx = mi * 2 + half;
            int row = wm + mi * 16 + half * 8 + (lane >> 2);
            float l = stl[row] + stl[128 + row];
            invl[idx] = 1.f / l;
            if (g == 0 && (lane & 3) == 0) {
                float2 ml; ml.x = m_t[idx]; ml.y = l;
                MLbuf[(long)z * 1024 + blockIdx.x * 128 + row] = ml;
            }
        }
    __syncthreads();

    float* ored = (float*)smem;
    if (g == 0) {
        #pragma unroll
        for (int mi = 0; mi < 2; mi++)
            #pragma unroll
            for (int ni = 0; ni < 8; ni++)
                #pragma unroll
                for (int half = 0; half < 2; half++) {
                    int row = wm + mi * 16 + half * 8 + (lane >> 2);
                    int col = ni * 8 + (lane & 3) * 2;
                    const float* a2 = oac + (mi * 8 + ni) * 4 + half * 2;
                    ored[row * 66 + col]     = a2[0];
                    ored[row * 66 + col + 1] = a2[1];
                }
    }
    __syncthreads();
    if (g == 1) {
        #pragma unroll
        for (int mi = 0; mi < 2; mi++)
            #pragma unroll
            for (int ni = 0; ni < 8; ni++)
                #pragma unroll
                for (int half = 0; half < 2; half++) {
                    int idx = mi * 2 + half;
                    int row = wm + mi * 16 + half * 8 + (lane >> 2);
                    int col = ni * 8 + (lane & 3) * 2;
                    const float* a2 = oac + (mi * 8 + ni) * 4 + half * 2;
                    float v0 = (ored[row * 66 + col]     + a2[0]) * invl[idx];
                    float v1 = (ored[row * 66 + col + 1] + a2[1]) * invl[idx];
                    bf16 h0, l0, h1, l1;
                    split1(v0, h0, l0); split1(v1, h1, l1);
                    *(uint32_t*)(Chb + (long)row * 512 + col) = pack_bf2(h0, h1);
                    *(uint32_t*)(Clb + (long)row * 512 + col) = pack_bf2(l0, l1);
                }
    }
}

// ================= corr factors: c = exp(m_used - m_fin) / l =================
__global__ void corr_kernel(const float* __restrict__ Mbuf,
                            const float2* __restrict__ MLbuf,
                            float* __restrict__ C)
{
    long i = (long)blockIdx.x * 256 + threadIdx.x;
    long z = i >> 13, q = i & 1023;
    float2 ml = MLbuf[z * 1024 + q];
    C[i] = __expf(Mbuf[i] - ml.x) / ml.y;
}

// ================= LayerNorm =================
__global__ void ln_kernel2(const float* __restrict__ x, const float* __restrict__ x2,
                           const float* __restrict__ w, const float* __restrict__ bb,
                           float* __restrict__ outf, bf16* __restrict__ ohi, bf16* __restrict__ olo)
{
    int row = blockIdx.x;
    int t = threadIdx.x;
    float4 v = ((const float4*)(x + (long)row * 512))[t];
    if (x2) {
        float4 v2 = ((const float4*)(x2 + (long)row * 512))[t];
        v.x += v2.x; v.y += v2.y; v.z += v2.z; v.w += v2.w;
    }
    float s  = v.x + v.y + v.z + v.w;
    float sq = v.x*v.x + v.y*v.y + v.z*v.z + v.w*v.w;
    #pragma unroll
    for (int o = 16; o > 0; o >>= 1) {
        s  += __shfl_xor_sync(0xffffffffu, s,  o);
        sq += __shfl_xor_sync(0xffffffffu, sq, o);
    }
    __shared__ float ss[4], ssq[4];
    int wid = t >> 5, lane = t & 31;
    if (lane == 0) { ss[wid] = s; ssq[wid] = sq; }
    __syncthreads();
    s  = ss[0]  + ss[1]  + ss[2]  + ss[3];
    sq = ssq[0] + ssq[1] + ssq[2] + ssq[3];
    float mu  = s * (1.0f / 512.0f);
    float var = sq * (1.0f / 512.0f) - mu * mu;
    float inv = rsqrtf(var + EPS);
    float4 wv = ((const float4*)w)[t];
    float4 bv = ((const float4*)bb)[t];
    float o4[4];
    o4[0] = (v.x - mu) * inv * wv.x + bv.x;
    o4[1] = (v.y - mu) * inv * wv.y + bv.y;
    o4[2] = (v.z - mu) * inv * wv.z + bv.z;
    o4[3] = (v.w - mu) * inv * wv.w + bv.w;
    long base = (long)row * 512 + t * 4;
    if (outf) *(float4*)(outf + base) = *(float4*)o4;
    if (ohi) {
        unsigned short hs[4], ls[4];
        #pragma unroll
        for (int j = 0; j < 4; j++) {
            bf16 h, l; split1(o4[j], h, l);
            hs[j] = __bfloat16_as_ushort(h);
            ls[j] = __bfloat16_as_ushort(l);
        }
        *(uint2*)(ohi + base) = *(uint2*)hs;
        *(uint2*)(olo + base) = *(uint2*)ls;
    }
}

// ================= split all 3 weight tensors in ONE launch =================
// float4 quads: in_w 196608, out_w 65536, ff_w 65536  (total 327680 -> 1280 blocks)
__global__ void split3_kernel(const float* __restrict__ in_w, bf16* __restrict__ inw_hi,
                              bf16* __restrict__ inw_lo,
                              const float* __restrict__ out_w, bf16* __restrict__ outw_hi,
                              bf16* __restrict__ outw_lo,
                              const float* __restrict__ ff_w, bf16* __restrict__ ffw_hi,
                              bf16* __restrict__ ffw_lo)
{
    long q = (long)blockIdx.x * 256 + threadIdx.x;   // quad index
    const float* src; bf16 *hi, *lo;
    if (q < 196608)      { src = in_w;  hi = inw_hi;  lo = inw_lo; }
    else if (q < 262144) { q -= 196608; src = out_w; hi = outw_hi; lo = outw_lo; }
    else                 { q -= 262144; src = ff_w;  hi = ffw_hi;  lo = ffw_lo; }
    long i = q * 4;
    float4 v = *(const float4*)(src + i);
    float a[4] = {v.x, v.y, v.z, v.w};
    unsigned short hs[4], ls[4];
    #pragma unroll
    for (int j = 0; j < 4; j++) {
        bf16 h, l; split1(a[j], h, l);
        hs[j] = __bfloat16_as_ushort(h);
        ls[j] = __bfloat16_as_ushort(l);
    }
    *(uint2*)(hi + i) = *(uint2*)hs;
    *(uint2*)(lo + i) = *(uint2*)ls;
}

// transpose V: vt[b][n][s] = v[b*1024+s][n], split to hi/lo
__global__ void transpose_v_kernel(const float* __restrict__ v,
                                   bf16* __restrict__ vhi, bf16* __restrict__ vlo)
{
    __shared__ float t[32][33];
    int b = blockIdx.z;
    int s0 = blockIdx.x * 32, n0 = blockIdx.y * 32;
    int tx = threadIdx.x, ty = threadIdx.y;
    #pragma unroll
    for (int i = 0; i < 4; i++) {
        int s = s0 + ty + i * 8;
        t[ty + i * 8][tx] = v[((long)b * 1024 + s) * 512 + n0 + tx];
    }
    __syncthreads();
    #pragma unroll
    for (int i = 0; i < 4; i++) {
        int n = n0 + ty + i * 8;
        float vv = t[tx][ty + i * 8];
        bf16 h, l; split1(vv, h, l);
        long o = (long)b * 512 * 1024 + (long)n * 1024 + s0 + tx;
        vhi[o] = h; vlo[o] = l;
    }
}

// ================= attn_weights = (1/8) sum_h c * P'' (fp16 P) =================
__global__ void mean_corr(const __half* __restrict__ P, const float* __restrict__ C,
                          float* __restrict__ out)
{
    long i = ((long)blockIdx.x * 256 + threadIdx.x) * 4;   // over 8M
    long b = i >> 20;
    long rem = i & 1048575;
    long q = rem >> 10;
    long k = rem & 1023;
    long t = k >> 7;
    const __half* p = P + (b << 23) + rem;
    float4 s = {0.f, 0.f, 0.f, 0.f};
    #pragma unroll
    for (int h = 0; h < 8; h++) {
        long z = b * 8 + h;
        float c = C[((z * 8 + t) << 10) + q];
        const __half2* p2 = (const __half2*)(p + ((long)h << 20));
        float2 v0 = __half22float2(p2[0]);
        float2 v1 = __half22float2(p2[1]);
        s.x += c * v0.x; s.y += c * v0.y; s.z += c * v1.x; s.w += c * v1.y;
    }
    s.x *= 0.125f; s.y *= 0.125f; s.z *= 0.125f; s.w *= 0.125f;
    *(float4*)(out + i) = s;
}

// ================= launch =================
extern "C" void kernel_launch(void* const* d_in, const int* in_sizes, int n_in,
                              void* d_out, int out_size)
{
    (void)in_sizes; (void)n_in; (void)out_size;
    const float* Zab   = (const float*)d_in[0];
    const float* Za    = (const float*)d_in[1];
    const float* ln_w  = (const float*)d_in[2];
    const float* ln_b  = (const float*)d_in[3];
    const float* in_w  = (const float*)d_in[4];
    const float* in_b  = (const float*)d_in[5];
    const float* out_w = (const float*)d_in[6];
    const float* out_b = (const float*)d_in[7];
    const float* ff_w  = (const float*)d_in[8];
    const float* ff_b  = (const float*)d_in[9];

    float* out_final = (float*)d_out;
    float* out_attnw = (float*)d_out + 8192L * 512;

    bf16 *qin_hi, *qin_lo, *kvin_hi, *kvin_lo, *inw_hi, *inw_lo;
    bf16 *outw_hi, *outw_lo, *ffw_hi, *ffw_lo, *q_hi, *q_lo;
    bf16 *k_hi, *k_lo, *vt_hi, *vt_lo, *ctx_hi, *ctx_lo, *xn_hi, *xn_lo;
    float *v, *x, *xn, *ff, *mb, *cb;
    __half* p;
    float2 *mlb;
    cudaGetSymbolAddress((void**)&qin_hi,  g_qin_hi);
    cudaGetSymbolAddress((void**)&qin_lo,  g_qin_lo);
    cudaGetSymbolAddress((void**)&kvin_hi, g_kvin_hi);
    cudaGetSymbolAddress((void**)&kvin_lo, g_kvin_lo);
    cudaGetSymbolAddress((void**)&inw_hi,  g_inw_hi);
    cudaGetSymbolAddress((void**)&inw_lo,  g_inw_lo);
    cudaGetSymbolAddress((void**)&outw_hi, g_outw_hi);
    cudaGetSymbolAddress((void**)&outw_lo, g_outw_lo);
    cudaGetSymbolAddress((void**)&ffw_hi,  g_ffw_hi);
    cudaGetSymbolAddress((void**)&ffw_lo,  g_ffw_lo);
    cudaGetSymbolAddress((void**)&q_hi,    g_q_hi);
    cudaGetSymbolAddress((void**)&q_lo,    g_q_lo);
    cudaGetSymbolAddress((void**)&k_hi,    g_k_hi);
    cudaGetSymbolAddress((void**)&k_lo,    g_k_lo);
    cudaGetSymbolAddress((void**)&vt_hi,   g_vt_hi);
    cudaGetSymbolAddress((void**)&vt_lo,   g_vt_lo);
    cudaGetSymbolAddress((void**)&ctx_hi,  g_ctx_hi);
    cudaGetSymbolAddress((void**)&ctx_lo,  g_ctx_lo);
    cudaGetSymbolAddress((void**)&xn_hi,   g_xn_hi);
    cudaGetSymbolAddress((void**)&xn_lo,   g_xn_lo);
    cudaGetSymbolAddress((void**)&v,   g_v);
    cudaGetSymbolAddress((void**)&p,   g_p);
    cudaGetSymbolAddress((void**)&x,   g_x);
    cudaGetSymbolAddress((void**)&xn,  g_xn);
    cudaGetSymbolAddress((void**)&ff,  g_ff);
    cudaGetSymbolAddress((void**)&mb,  g_m);
    cudaGetSymbolAddress((void**)&mlb, g_ml);
    cudaGetSymbolAddress((void**)&cb,  g_c);

    const int SMEM_PI  = 2 * (2 * 128 * 80 + 2 * 128 * 80);           // 81920
    const int SMEM_ATT = 6 * 128 * 144 + 4 * 64 * 272 + 2048;         // 182272
    cudaFuncSetAttribute((const void*)proj_qkv,
                         cudaFuncAttributeMaxDynamicSharedMemorySize, SMEM_PI);
    cudaFuncSetAttribute((const void*)gemm_pi,
                         cudaFuncAttributeMaxDynamicSharedMemorySize, SMEM_PI);
    cudaFuncSetAttribute((const void*)attn_flash,
                         cudaFuncAttributeMaxDynamicSharedMemorySize, SMEM_ATT);

    // 1) LN of inputs -> bf16 hi/lo
    ln_kernel2<<<8192, 128>>>(Zab, nullptr, ln_w, ln_b, nullptr, qin_hi, qin_lo);
    ln_kernel2<<<8192, 128>>>(Za,  nullptr, ln_w, ln_b, nullptr, kvin_hi, kvin_lo);

    // 2) split all weights in one launch
    split3_kernel<<<1280, 256>>>(in_w, inw_hi, inw_lo,
                                 out_w, outw_hi, outw_lo,
                                 ff_w, ffw_hi, ffw_lo);

    // 3) fused q/k/v projections (one launch, grid.z selects)
    proj_qkv<<<dim3(4, 64, 3), 256, SMEM_PI>>>(
        qin_hi, qin_lo, kvin_hi, kvin_lo, inw_hi, inw_lo, in_b,
        q_hi, q_lo, k_hi, k_lo, v);

    // 4) V -> transposed hi/lo
    transpose_v_kernel<<<dim3(32, 16, 8), dim3(32, 8)>>>(v, vt_hi, vt_lo);

    // 5) single-pass flash attention -> P'' fp16, m/ml bufs, ctx hi/lo
    attn_flash<<<dim3(8, 1, 64), 256, SMEM_ATT>>>(
        q_hi, q_lo, k_hi, k_lo, vt_hi, vt_lo, p, mb, mlb, ctx_hi, ctx_lo);

    // 6) corr factors, then attn_weights = (1/8) sum_h c * P''
    corr_kernel<<<2048, 256>>>(mb, mlb, cb);
    mean_corr<<<8192, 256>>>(p, cb, out_attnw);

    // 7) x = ctx @ Wo^T + bo + Zab
    gemm_pi<<<dim3(4, 64, 1), 256, SMEM_PI>>>(
        ctx_hi, ctx_lo, outw_hi, outw_lo,
        x, nullptr, nullptr, 1.0f, out_b, Zab);

    // 8) x_n = LN(x)
    ln_kernel2<<<8192, 128>>>(x, nullptr, ln_w, ln_b, xn, xn_hi, xn_lo);

    // 9) ff = x_n @ ff_w^T + ff_b
    gemm_pi<<<dim3(4, 64, 1), 256, SMEM_PI>>>(
        xn_hi, xn_lo, ffw_hi, ffw_lo,
        ff, nullptr, nullptr, 1.0f, ff_b, nullptr);

    // 10) final = LN(x_n + ff) -> d_out
    ln_kernel2<<<8192, 128>>>(xn, ff, ln_w, ln_b, out_final, nullptr, nullptr);
}

// round 14
// speedup vs baseline: 1.0007x; 1.0007x over previous
#include <cuda_runtime.h>
#include <cuda_bf16.h>
#include <cuda_fp16.h>
#include <cstdint>

#define EPS 1e-5f
typedef __nv_bfloat16 bf16;

// ================= scratch (no allocation allowed) =================
__device__ bf16  g_qin_hi [8192L * 512];
__device__ bf16  g_qin_lo [8192L * 512];
__device__ bf16  g_kvin_hi[8192L * 512];
__device__ bf16  g_kvin_lo[8192L * 512];
__device__ bf16  g_inw_hi [1536L * 512];
__device__ bf16  g_inw_lo [1536L * 512];
__device__ bf16  g_outw_hi[512L * 512];
__device__ bf16  g_outw_lo[512L * 512];
__device__ bf16  g_ffw_hi [512L * 512];
__device__ bf16  g_ffw_lo [512L * 512];
__device__ bf16  g_q_hi   [8192L * 512];
__device__ bf16  g_q_lo   [8192L * 512];
__device__ float g_v      [8192L * 512];
__device__ bf16  g_k_hi   [8192L * 512];
__device__ bf16  g_k_lo   [8192L * 512];
__device__ bf16  g_vt_hi  [8L * 512 * 1024];
__device__ bf16  g_vt_lo  [8L * 512 * 1024];
__device__ __half g_p     [64LL * 1024 * 1024];   // unnormalized exp, fp16, 128 MB
__device__ float g_m      [64L * 8 * 1024];       // m used per (z, tile128, qrow)
__device__ float2 g_ml    [64L * 1024];           // final (m, l) per (z, qrow)
__device__ float g_c      [64L * 8 * 1024];       // corr = exp(m_used-m)/l
__device__ bf16  g_ctx_hi [8192L * 512];
__device__ bf16  g_ctx_lo [8192L * 512];
__device__ float g_x      [8192L * 512];
__device__ float g_xn     [8192L * 512];
__device__ bf16  g_xn_hi  [8192L * 512];
__device__ bf16  g_xn_lo  [8192L * 512];
__device__ float g_ff     [8192L * 512];

// ================= helpers =================
__device__ __forceinline__ uint32_t smem_u32(const void* p){
    uint32_t a;
    asm("{ .reg .u64 t; cvta.to.shared.u64 t, %1; cvt.u32.u64 %0, t; }" : "=r"(a) : "l"(p));
    return a;
}
#define CP_ASYNC16(dst, src) \
    asm volatile("cp.async.cg.shared.global [%0], [%1], 16;" :: "r"(dst), "l"(src))
#define CP_COMMIT() asm volatile("cp.async.commit_group;" ::: "memory")
#define CP_WAIT(n)  asm volatile("cp.async.wait_group %0;" :: "n"(n) : "memory")

__device__ __forceinline__ void ldsm4(uint32_t addr, uint32_t& r0, uint32_t& r1,
                                      uint32_t& r2, uint32_t& r3){
    asm volatile("ldmatrix.sync.aligned.m8n8.x4.shared.b16 {%0,%1,%2,%3}, [%4];"
                 : "=r"(r0), "=r"(r1), "=r"(r2), "=r"(r3) : "r"(addr));
}
__device__ __forceinline__ void mma16816(float* d, const uint32_t* a, const uint32_t* b){
    asm volatile("mma.sync.aligned.m16n8k16.row.col.f32.bf16.bf16.f32 "
                 "{%0,%1,%2,%3},{%4,%5,%6,%7},{%8,%9},{%0,%1,%2,%3};"
                 : "+f"(d[0]), "+f"(d[1]), "+f"(d[2]), "+f"(d[3])
                 : "r"(a[0]), "r"(a[1]), "r"(a[2]), "r"(a[3]), "r"(b[0]), "r"(b[1]));
}
__device__ __forceinline__ void split1(float v, bf16& h, bf16& l){
    h = __float2bfloat16_rn(v);
    l = __float2bfloat16_rn(v - __bfloat162float(h));
}
__device__ __forceinline__ uint32_t pack_bf2(bf16 a, bf16 b){
    return (uint32_t)__bfloat16_as_ushort(a) | ((uint32_t)__bfloat16_as_ushort(b) << 16);
}

// ================= shared GEMM mainloop =================
struct GemmOut {
    float* C; bf16 *Chi, *Clo;
    const float* bias; const float* resid;
    float scale;
};

__device__ __forceinline__ void gemm_core(
    const bf16* Ah, const bf16* Al, long lda,
    const bf16* Bh, const bf16* Bl, long ldb,
    int K, char* smem, int tid, float* acc /*2*8*4*/)
{
    constexpr int ROWB = 80;
    constexpr int ASZ = 128 * ROWB;
    constexpr int BSZ = 128 * ROWB;
    constexpr int STAGE = 2 * ASZ + 2 * BSZ;
    const int wid = tid >> 5, lane = tid & 31;
    const int wm = (wid & 3) * 32, wn = (wid >> 2) * 64;
    const uint32_t sb = smem_u32(smem);

    auto loadc = [&](int kc, int s){
        long k0 = (long)kc * 32;
        uint32_t base = sb + s * STAGE;
        #pragma unroll
        for (int i = 0; i < 2; i++) {
            int id = tid + i * 256; int r = id >> 2, c = id & 3;
            CP_ASYNC16(base + r * ROWB + c * 16,       Ah + (long)r * lda + k0 + c * 8);
            CP_ASYNC16(base + ASZ + r * ROWB + c * 16, Al + (long)r * lda + k0 + c * 8);
            CP_ASYNC16(base + 2*ASZ + r * ROWB + c * 16,       Bh + (long)r * ldb + k0 + c * 8);
            CP_ASYNC16(base + 2*ASZ + BSZ + r * ROWB + c * 16, Bl + (long)r * ldb + k0 + c * 8);
        }
        CP_COMMIT();
    };

    const int arow = (lane & 7) + ((lane & 8)  ? 8 : 0);
    const int acol = (lane & 16) ? 8 : 0;
    const int brow = (lane & 7) + ((lane & 16) ? 8 : 0);
    const int bcol = (lane & 8) ? 8 : 0;

    const int KC = K >> 5;
    loadc(0, 0);
    for (int kc = 0; kc < KC; kc++) {
        int s = kc & 1;
        if (kc + 1 < KC) { loadc(kc + 1, s ^ 1); CP_WAIT(1); }
        else             { CP_WAIT(0); }
        __syncthreads();
        uint32_t base = sb + s * STAGE;
        #pragma unroll
        for (int ph = 0; ph < 3; ph++) {
            uint32_t abuf = base + ((ph == 1) ? ASZ : 0);
            uint32_t bbuf = base + 2*ASZ + ((ph == 2) ? BSZ : 0);
            #pragma unroll
            for (int k16 = 0; k16 < 2; k16++) {
                uint32_t af[2][4];
                #pragma unroll
                for (int mi = 0; mi < 2; mi++)
                    ldsm4(abuf + (wm + mi * 16 + arow) * ROWB + (k16 * 16 + acol) * 2,
                          af[mi][0], af[mi][1], af[mi][2], af[mi][3]);
                uint32_t bfr[4][4];
                #pragma unroll
                for (int n2 = 0; n2 < 4; n2++)
                    ldsm4(bbuf + (wn + n2 * 16 + brow) * ROWB + (k16 * 16 + bcol) * 2,
                          bfr[n2][0], bfr[n2][1], bfr[n2][2], bfr[n2][3]);
                #pragma unroll
                for (int mi = 0; mi < 2; mi++)
                    #pragma unroll
                    for (int ni = 0; ni < 8; ni++)
                        mma16816(acc + (mi * 8 + ni) * 4, af[mi], bfr[ni >> 1] + (ni & 1) * 2);
            }
        }
        __syncthreads();
    }
}

__device__ __forceinline__ void gemm_epi(
    const float* acc, long bm, long bn, long ldc, long cbase,
    const GemmOut& o, int tid)
{
    const int wid = tid >> 5, lane = tid & 31;
    const int wm = (wid & 3) * 32, wn = (wid >> 2) * 64;
    #pragma unroll
    for (int mi = 0; mi < 2; mi++) {
        #pragma unroll
        for (int ni = 0; ni < 8; ni++) {
            const float* a4 = acc + (mi * 8 + ni) * 4;
            int n0 = (int)bn + wn + ni * 8 + (lane & 3) * 2;
            #pragma unroll
            for (int half = 0; half < 2; half++) {
                long m = bm + wm + mi * 16 + (lane >> 2) + half * 8;
                float v0 = a4[half * 2 + 0];
                float v1 = a4[half * 2 + 1];
                if (o.bias) { v0 += o.bias[n0]; v1 += o.bias[n0 + 1]; }
                v0 *= o.scale; v1 *= o.scale;
                if (o.resid) {
                    float2 rr = *(const float2*)(o.resid + cbase + m * ldc + n0);
                    v0 += rr.x; v1 += rr.y;
                }
                if (o.C) {
                    float2 ov; ov.x = v0; ov.y = v1;
                    *(float2*)(o.C + cbase + m * ldc + n0) = ov;
                }
                if (o.Chi) {
                    bf16 h0, l0, h1, l1;
                    split1(v0, h0, l0); split1(v1, h1, l1);
                    *(uint32_t*)(o.Chi + cbase + m * ldc + n0) = pack_bf2(h0, h1);
                    *(uint32_t*)(o.Clo + cbase + m * ldc + n0) = pack_bf2(l0, l1);
                }
            }
        }
    }
}

// ================= fused q/k/v projections: grid.z selects which =================
__global__ void __launch_bounds__(256)
proj_qkv(const bf16* __restrict__ qinh, const bf16* __restrict__ qinl,
         const bf16* __restrict__ kvinh, const bf16* __restrict__ kvinl,
         const bf16* __restrict__ inwh, const bf16* __restrict__ inwl,
         const float* __restrict__ in_b,
         bf16* __restrict__ qh, bf16* __restrict__ ql,
         bf16* __restrict__ kh, bf16* __restrict__ kl,
         float* __restrict__ v)
{
    extern __shared__ char smem[];
    const int tid = threadIdx.x;
    const int z = blockIdx.z;
    long bm = (long)blockIdx.y * 128;
    long bn = (long)blockIdx.x * 128;

    const bf16 *Ah, *Al;
    GemmOut o{nullptr, nullptr, nullptr, nullptr, nullptr, 1.0f};
    if (z == 0) { Ah = qinh;  Al = qinl;  o.Chi = qh; o.Clo = ql; o.scale = 0.125f; o.bias = in_b; }
    else if (z == 1) { Ah = kvinh; Al = kvinl; o.Chi = kh; o.Clo = kl; o.bias = in_b + 512; }
    else { Ah = kvinh; Al = kvinl; o.C = v; o.bias = in_b + 1024; }
    const bf16* Bh = inwh + (long)z * 512 * 512 + bn * 512;
    const bf16* Bl = inwl + (long)z * 512 * 512 + bn * 512;

    float acc[64];
    #pragma unroll
    for (int i = 0; i < 64; i++) acc[i] = 0.f;
    gemm_core(Ah + bm * 512, Al + bm * 512, 512, Bh, Bl, 512, 512, smem, tid, acc);
    gemm_epi(acc, bm, bn, 512, 0, o, tid);
}

// ================= generic GEMM (out-proj / ff) =================
__global__ void __launch_bounds__(256)
gemm_pi(const bf16* __restrict__ Ahi, const bf16* __restrict__ Alo,
        const bf16* __restrict__ Bhi, const bf16* __restrict__ Blo,
        float* __restrict__ C, bf16* __restrict__ Chi, bf16* __restrict__ Clo,
        float scale, const float* __restrict__ bias, const float* __restrict__ resid)
{
    extern __shared__ char smem[];
    const int tid = threadIdx.x;
    long bm = (long)blockIdx.y * 128;
    long bn = (long)blockIdx.x * 128;
    float acc[64];
    #pragma unroll
    for (int i = 0; i < 64; i++) acc[i] = 0.f;
    gemm_core(Ahi + bm * 512, Alo + bm * 512, 512,
              Bhi + bn * 512, Blo + bn * 512, 512, 512, smem, tid, acc);
    GemmOut o{C, Chi, Clo, bias, resid, scale};
    gemm_epi(acc, bm, bn, 512, 0, o, tid);
}

// ================= single-pass flash attention (P out as fp16) =================
__global__ void __launch_bounds__(256)
attn_flash(const bf16* __restrict__ qhi, const bf16* __restrict__ qlo,
           const bf16* __restrict__ khi, const bf16* __restrict__ klo,
           const bf16* __restrict__ vhi, const bf16* __restrict__ vlo,
           __half* __restrict__ P, float* __restrict__ Mbuf,
           float2* __restrict__ MLbuf,
           bf16* __restrict__ ctxhi, bf16* __restrict__ ctxlo)
{
    constexpr int PITCH  = 144;
    constexpr int PLANE  = 128 * PITCH;
    constexpr int VPITCH = 272;
    constexpr int VPLANE = 64 * VPITCH;
    extern __shared__ char smem[];
    const uint32_t sb  = smem_u32(smem);
    const uint32_t sQH = sb;
    const uint32_t sQL = sb + PLANE;
    const uint32_t sK0 = sb + 2 * PLANE;
    const uint32_t sV0 = sb + 6 * PLANE;
    float* stm = (float*)(smem + 6 * PLANE + 4 * VPLANE);        // [2][128]
    float* stl = (float*)(smem + 6 * PLANE + 4 * VPLANE + 1024);

    const int tid = threadIdx.x, wid = tid >> 5, lane = tid & 31;
    const int wm = (wid & 3) * 32, wn = (wid >> 2) * 64;
    const int g = wid >> 2;
    const int z = blockIdx.z, b_ = z >> 3, h_ = z & 7;
    const long qrow0 = (long)b_ * 1024 + blockIdx.x * 128;
    const bf16* Qh = qhi + qrow0 * 512 + h_ * 64;
    const bf16* Ql = qlo + qrow0 * 512 + h_ * 64;
    const bf16* Kh = khi + (long)b_ * 1024 * 512 + h_ * 64;
    const bf16* Kl = klo + (long)b_ * 1024 * 512 + h_ * 64;
    const bf16* Vh = vhi + (long)b_ * 512 * 1024 + (long)h_ * 64 * 1024;
    const bf16* Vl = vlo + (long)b_ * 512 * 1024 + (long)h_ * 64 * 1024;
    __half* Pz = P + ((long)z << 20) + (long)blockIdx.x * 128 * 1024;
    bf16* Chb = ctxhi + qrow0 * 512 + h_ * 64;
    bf16* Clb = ctxlo + qrow0 * 512 + h_ * 64;

    #pragma unroll
    for (int i = 0; i < 4; i++) {
        int id = tid + i * 256; int r = id >> 3, c = id & 7;
        CP_ASYNC16(sQH + r * PITCH + c * 16, Qh + (long)r * 512 + c * 8);
        CP_ASYNC16(sQL + r * PITCH + c * 16, Ql + (long)r * 512 + c * 8);
    }
    auto loadK = [&](int kt, int s){
        uint32_t dh = sK0 + s * 2 * PLANE, dl = dh + PLANE;
        const bf16* sh = Kh + (long)kt * 128 * 512;
        const bf16* sl = Kl + (long)kt * 128 * 512;
        #pragma unroll
        for (int i = 0; i < 4; i++) {
            int id = tid + i * 256; int r = id >> 3, c = id & 7;
            CP_ASYNC16(dh + r * PITCH + c * 16, sh + (long)r * 512 + c * 8);
            CP_ASYNC16(dl + r * PITCH + c * 16, sl + (long)r * 512 + c * 8);
        }
    };
    auto loadV = [&](int kt, int s){
        uint32_t dh = sV0 + s * 2 * VPLANE, dl = dh + VPLANE;
        const bf16* sh = Vh + (long)kt * 128;
        const bf16* sl = Vl + (long)kt * 128;
        #pragma unroll
        for (int i = 0; i < 4; i++) {
            int id = tid + i * 256; int r = id >> 4, c = id & 15;
            CP_ASYNC16(dh + r * VPITCH + c * 16, sh + (long)r * 1024 + c * 8);
            CP_ASYNC16(dl + r * VPITCH + c * 16, sl + (long)r * 1024 + c * 8);
        }
    };
    loadK(0, 0); loadV(0, 0);
    CP_COMMIT();

    const int arow = (lane & 7) + ((lane & 8)  ? 8 : 0);
    const int acol = (lane & 16) ? 8 : 0;
    const int brow = (lane & 7) + ((lane & 16) ? 8 : 0);
    const int bcol = (lane & 8) ? 8 : 0;

    float m_t[4], l_t[4];
    #pragma unroll
    for (int i = 0; i < 4; i++) { m_t[i] = -1e30f; l_t[i] = 0.f; }

    float oac[64];
    #pragma unroll
    for (int i = 0; i < 64; i++) oac[i] = 0.f;

    float acc[64];

    for (int t = 0; t < 8; t++) {
        int s = t & 1;
        if (t + 1 < 8) {
            loadK(t + 1, s ^ 1); loadV(t + 1, s ^ 1);
            CP_COMMIT(); CP_WAIT(1);
        } else {
            CP_WAIT(0);
        }
        __syncthreads();

        #pragma unroll
        for (int i = 0; i < 64; i++) acc[i] = 0.f;
        uint32_t kbase = sK0 + s * 2 * PLANE;
        #pragma unroll
        for (int ph = 0; ph < 3; ph++) {
            uint32_t abuf = (ph == 1) ? sQL : sQH;
            uint32_t bbuf = kbase + ((ph == 2) ? PLANE : 0);
            #pragma unroll
            for (int k16 = 0; k16 < 4; k16++) {
                uint32_t af[2][4];
                #pragma unroll
                for (int mi = 0; mi < 2; mi++)
                    ldsm4(abuf + (wm + mi * 16 + arow) * PITCH + (k16 * 16 + acol) * 2,
                          af[mi][0], af[mi][1], af[mi][2], af[mi][3]);
                uint32_t bfr[4][4];
                #pragma unroll
                for (int n2 = 0; n2 < 4; n2++)
                    ldsm4(bbuf + (n2 * 16 + brow) * PITCH + (k16 * 16 + bcol) * 2 + wn * PITCH,
                          bfr[n2][0], bfr[n2][1], bfr[n2][2], bfr[n2][3]);
                #pragma unroll
                for (int mi = 0; mi < 2; mi++)
                    #pragma unroll
                    for (int ni = 0; ni < 8; ni++)
                        mma16816(acc + (mi * 8 + ni) * 4, af[mi], bfr[ni >> 1] + (ni & 1) * 2);
            }
        }

        float tmax[4];
        #pragma unroll
        for (int mi = 0; mi < 2; mi++)
            #pragma unroll
            for (int half = 0; half < 2; half++) {
                int idx = mi * 2 + half;
                float vm = -1e30f;
                #pragma unroll
                for (int ni = 0; ni < 8; ni++) {
                    const float* a2 = acc + (mi * 8 + ni) * 4 + half * 2;
                    vm = fmaxf(vm, fmaxf(a2[0], a2[1]));
                }
                vm = fmaxf(vm, __shfl_xor_sync(0xffffffffu, vm, 1));
                vm = fmaxf(vm, __shfl_xor_sync(0xffffffffu, vm, 2));
                tmax[idx] = vm;
            }
        if ((lane & 3) == 0) {
            #pragma unroll
            for (int mi = 0; mi < 2; mi++)
                #pragma unroll
                for (int half = 0; half < 2; half++) {
                    int row = wm + mi * 16 + half * 8 + (lane >> 2);
                    stm[g * 128 + row] = tmax[mi * 2 + half];
                }
        }
        __syncthreads();

        float alpha[4], mnew[4];
        #pragma unroll
        for (int mi = 0; mi < 2; mi++)
            #pragma unroll
            for (int half = 0; half < 2; half++) {
                int idx = mi * 2 + half;
                int row = wm + mi * 16 + half * 8 + (lane >> 2);
                float tm = fmaxf(stm[row], stm[128 + row]);
                float mn = fmaxf(m_t[idx], tm);
                alpha[idx] = __expf(m_t[idx] - mn);
                mnew[idx] = mn;
                m_t[idx] = mn;
            }
        if (g == 0 && (lane & 3) == 0) {
            #pragma unroll
            for (int mi = 0; mi < 2; mi++)
                #pragma unroll
                for (int half = 0; half < 2; half++) {
                    int row = wm + mi * 16 + half * 8 + (lane >> 2);
                    Mbuf[(((long)z * 8 + t) << 10) + blockIdx.x * 128 + row] = mnew[mi * 2 + half];
                }
        }

        #pragma unroll
        for (int mi = 0; mi < 2; mi++)
            #pragma unroll
            for (int ni = 0; ni < 8; ni++)
                #pragma unroll
                for (int half = 0; half < 2; half++) {
                    float* o2 = oac + (mi * 8 + ni) * 4 + half * 2;
                    float a = alpha[mi * 2 + half];
                    o2[0] *= a; o2[1] *= a;
                }

        #pragma unroll
        for (int mi = 0; mi < 2; mi++)
            #pragma unroll
            for (int half = 0; half < 2; half++) {
                int idx = mi * 2 + half;
                float sum = 0.f;
                #pragma unroll
                for (int ni = 0; ni < 8; ni++) {
                    float* a2 = acc + (mi * 8 + ni) * 4 + half * 2;
                    a2[0] = __expf(a2[0] - mnew[idx]);
                    a2[1] = __expf(a2[1] - mnew[idx]);
                    sum += a2[0] + a2[1];
                }
                l_t[idx] = l_t[idx] * alpha[idx] + sum;
            }
        // write P'' as fp16
        #pragma unroll
        for (int mi = 0; mi < 2; mi++)
            #pragma unroll
            for (int ni = 0; ni < 8; ni++)
                #pragma unroll
                for (int half = 0; half < 2; half++) {
                    int row = wm + mi * 16 + half * 8 + (lane >> 2);
                    int n0 = t * 128 + wn + ni * 8 + (lane & 3) * 2;
                    const float* a2 = acc + (mi * 8 + ni) * 4 + half * 2;
                    __half2 o2 = __floats2half2_rn(a2[0], a2[1]);
                    *(__half2*)(Pz + (long)row * 1024 + n0) = o2;
                }

        uint32_t vb = sV0 + s * 2 * VPLANE;
        #pragma unroll
        for (int j = 0; j < 4; j++) {
            uint32_t ah[2][4], al[2][4];
            #pragma unroll
            for (int mi = 0; mi < 2; mi++) {
                const float* t0 = acc + (mi * 8 + 2 * j) * 4;
                const float* t1 = acc + (mi * 8 + 2 * j + 1) * 4;
                #pragma unroll
                for (int r = 0; r < 2; r++) {
                    bf16 h0, l0, h1, l1;
                    split1(t0[r * 2 + 0], h0, l0);
                    split1(t0[r * 2 + 1], h1, l1);
                    ah[mi][r] = pack_bf2(h0, h1);
                    al[mi][r] = pack_bf2(l0, l1);
                    bf16 g0, m0, g1, m1;
                    split1(t1[r * 2 + 0], g0, m0);
                    split1(t1[r * 2 + 1], g1, m1);
                    ah[mi][2 + r] = pack_bf2(g0, g1);
                    al[mi][2 + r] = pack_bf2(m0, m1);
                }
            }
            uint32_t bfr[4][4];
            #pragma unroll
            for (int n2 = 0; n2 < 4; n2++)
                ldsm4(vb + (n2 * 16 + brow) * VPITCH + (wn + j * 16 + bcol) * 2,
                      bfr[n2][0], bfr[n2][1], bfr[n2][2], bfr[n2][3]);
            #pragma unroll
            for (int mi = 0; mi < 2; mi++)
                #pragma unroll
                for (int ni = 0; ni < 8; ni++) {
                    mma16816(oac + (mi * 8 + ni) * 4, ah[mi], bfr[ni >> 1] + (ni & 1) * 2);
                    mma16816(oac + (mi * 8 + ni) * 4, al[mi], bfr[ni >> 1] + (ni & 1) * 2);
                }
            #pragma unroll
            for (int n2 = 0; n2 < 4; n2++)
                ldsm4(vb + VPLANE + (n2 * 16 + brow) * VPITCH + (wn + j * 16 + bcol) * 2,
                      bfr[n2][0], bfr[n2][1], bfr[n2][2], bfr[n2][3]);
            #pragma unroll
            for (int mi = 0; mi < 2; mi++)
                #pragma unroll
                for (int ni = 0; ni < 8; ni++)
                    mma16816(oac + (mi * 8 + ni) * 4, ah[mi], bfr[ni >> 1] + (ni & 1) * 2);
        }
        __syncthreads();
    }

    #pragma unroll
    for (int idx = 0; idx < 4; idx++) {
        l_t[idx] += __shfl_xor_sync(0xffffffffu, l_t[idx], 1);
        l_t[idx] += __shfl_xor_sync(0xffffffffu, l_t[idx], 2);
    }
    if ((lane & 3) == 0) {
        #pragma unroll
        for (int mi = 0; mi < 2; mi++)
            #pragma unroll
            for (int half = 0; half < 2; half++) {
                int row = wm + mi * 16 + half * 8 + (lane >> 2);
                stl[g * 128 + row] = l_t[mi * 2 + half];
            }
    }
    __syncthreads();
    float invl[4];
    #pragma unroll
    for (int mi = 0; mi < 2; mi++)
        #pragma unroll
        for (int half = 0; half < 2; half++) {
            int idx = mi * 2 + half;
            int row = wm + mi * 16 + half * 8 + (lane >> 2);
            float l = stl[row] + stl[128 + row];
            invl[idx] = 1.f / l;
            if (g == 0 && (lane & 3) == 0) {
                float2 ml; ml.x = m_t[idx]; ml.y = l;
                MLbuf[(long)z * 1024 + blockIdx.x * 128 + row] = ml;
            }
        }
    __syncthreads();

    float* ored = (float*)smem;
    if (g == 0) {
        #pragma unroll
        for (int mi = 0; mi < 2; mi++)
            #pragma unroll
            for (int ni = 0; ni < 8; ni++)
                #pragma unroll
                for (int half = 0; half < 2; half++) {
                    int row = wm + mi * 16 + half * 8 + (lane >> 2);
                    int col = ni * 8 + (lane & 3) * 2;
                    const float* a2 = oac + (mi * 8 + ni) * 4 + half * 2;
                    ored[row * 66 + col]     = a2[0];
                    ored[row * 66 + col + 1] = a2[1];
                }
    }
    __syncthreads();
    if (g == 1) {
        #pragma unroll
        for (int mi = 0; mi < 2; mi++)
            #pragma unroll
            for (int ni = 0; ni < 8; ni++)
                #pragma unroll
                for (int half = 0; half < 2; half++) {
                    int idx = mi * 2 + half;
                    int row = wm + mi * 16 + half * 8 + (lane >> 2);
                    int col = ni * 8 + (lane & 3) * 2;
                    const float* a2 = oac + (mi * 8 + ni) * 4 + half * 2;
                    float v0 = (ored[row * 66 + col]     + a2[0]) * invl[idx];
                    float v1 = (ored[row * 66 + col + 1] + a2[1]) * invl[idx];
                    bf16 h0, l0, h1, l1;
                    split1(v0, h0, l0); split1(v1, h1, l1);
                    *(uint32_t*)(Chb + (long)row * 512 + col) = pack_bf2(h0, h1);
                    *(uint32_t*)(Clb + (long)row * 512 + col) = pack_bf2(l0, l1);
                }
    }
}

// ================= corr factors: c = exp(m_used - m_fin) / l =================
__global__ void corr_kernel(const float* __restrict__ Mbuf,
                            const float2* __restrict__ MLbuf,
                            float* __restrict__ C)
{
    long i = (long)blockIdx.x * 256 + threadIdx.x;
    long z = i >> 13, q = i & 1023;
    float2 ml = MLbuf[z * 1024 + q];
    C[i] = __expf(Mbuf[i] - ml.x) / ml.y;
}

// ================= LayerNorm =================
__global__ void ln_kernel2(const float* __restrict__ x, const float* __restrict__ x2,
                           const float* __restrict__ w, const float* __restrict__ bb,
                           float* __restrict__ outf, bf16* __restrict__ ohi, bf16* __restrict__ olo)
{
    int row = blockIdx.x;
    int t = threadIdx.x;
    float4 v = ((const float4*)(x + (long)row * 512))[t];
    if (x2) {
        float4 v2 = ((const float4*)(x2 + (long)row * 512))[t];
        v.x += v2.x; v.y += v2.y; v.z += v2.z; v.w += v2.w;
    }
    float s  = v.x + v.y + v.z + v.w;
    float sq = v.x*v.x + v.y*v.y + v.z*v.z + v.w*v.w;
    #pragma unroll
    for (int o = 16; o > 0; o >>= 1) {
        s  += __shfl_xor_sync(0xffffffffu, s,  o);
        sq += __shfl_xor_sync(0xffffffffu, sq, o);
    }
    __shared__ float ss[4], ssq[4];
    int wid = t >> 5, lane = t & 31;
    if (lane == 0) { ss[wid] = s; ssq[wid] = sq; }
    __syncthreads();
    s  = ss[0]  + ss[1]  + ss[2]  + ss[3];
    sq = ssq[0] + ssq[1] + ssq[2] + ssq[3];
    float mu  = s * (1.0f / 512.0f);
    float var = sq * (1.0f / 512.0f) - mu * mu;
    float inv = rsqrtf(var + EPS);
    float4 wv = ((const float4*)w)[t];
    float4 bv = ((const float4*)bb)[t];
    float o4[4];
    o4[0] = (v.x - mu) * inv * wv.x + bv.x;
    o4[1] = (v.y - mu) * inv * wv.y + bv.y;
    o4[2] = (v.z - mu) * inv * wv.z + bv.z;
    o4[3] = (v.w - mu) * inv * wv.w + bv.w;
    long base = (long)row * 512 + t * 4;
    if (outf) *(float4*)(outf + base) = *(float4*)o4;
    if (ohi) {
        unsigned short hs[4], ls[4];
        #pragma unroll
        for (int j = 0; j < 4; j++) {
            bf16 h, l; split1(o4[j], h, l);
            hs[j] = __bfloat16_as_ushort(h);
            ls[j] = __bfloat16_as_ushort(l);
        }
        *(uint2*)(ohi + base) = *(uint2*)hs;
        *(uint2*)(olo + base) = *(uint2*)ls;
    }
}

// ================= split all 3 weight tensors in ONE launch =================
// float4 quads: in_w 196608, out_w 65536, ff_w 65536  (total 327680 -> 1280 blocks)
__global__ void split3_kernel(const float* __restrict__ in_w, bf16* __restrict__ inw_hi,
                              bf16* __restrict__ inw_lo,
                              const float* __restrict__ out_w, bf16* __restrict__ outw_hi,
                              bf16* __restrict__ outw_lo,
                              const float* __restrict__ ff_w, bf16* __restrict__ ffw_hi,
                              bf16* __restrict__ ffw_lo)
{
    long q = (long)blockIdx.x * 256 + threadIdx.x;   // quad index
    const float* src; bf16 *hi, *lo;
    if (q < 196608)      { src = in_w;  hi = inw_hi;  lo = inw_lo; }
    else if (q < 262144) { q -= 196608; src = out_w; hi = outw_hi; lo = outw_lo; }
    else                 { q -= 262144; src = ff_w;  hi = ffw_hi;  lo = ffw_lo; }
    long i = q * 4;
    float4 v = *(const float4*)(src + i);
    float a[4] = {v.x, v.y, v.z, v.w};
    unsigned short hs[4], ls[4];
    #pragma unroll
    for (int j = 0; j < 4; j++) {
        bf16 h, l; split1(a[j], h, l);
        hs[j] = __bfloat16_as_ushort(h);
        ls[j] = __bfloat16_as_ushort(l);
    }
    *(uint2*)(hi + i) = *(uint2*)hs;
    *(uint2*)(lo + i) = *(uint2*)ls;
}

// transpose V: vt[b][n][s] = v[b*1024+s][n], split to hi/lo
__global__ void transpose_v_kernel(const float* __restrict__ v,
                                   bf16* __restrict__ vhi, bf16* __restrict__ vlo)
{
    __shared__ float t[32][33];
    int b = blockIdx.z;
    int s0 = blockIdx.x * 32, n0 = blockIdx.y * 32;
    int tx = threadIdx.x, ty = threadIdx.y;
    #pragma unroll
    for (int i = 0; i < 4; i++) {
        int s = s0 + ty + i * 8;
        t[ty + i * 8][tx] = v[((long)b * 1024 + s) * 512 + n0 + tx];
    }
    __syncthreads();
    #pragma unroll
    for (int i = 0; i < 4; i++) {
        int n = n0 + ty + i * 8;
        float vv = t[tx][ty + i * 8];
        bf16 h, l; split1(vv, h, l);
        long o = (long)b * 512 * 1024 + (long)n * 1024 + s0 + tx;
        vhi[o] = h; vlo[o] = l;
    }
}

// ================= attn_weights = (1/8) sum_h c * P'' (fp16 P) =================
__global__ void mean_corr(const __half* __restrict__ P, const float* __restrict__ C,
                          float* __restrict__ out)
{
    long i = ((long)blockIdx.x * 256 + threadIdx.x) * 4;   // over 8M
    long b = i >> 20;
    long rem = i & 1048575;
    long q = rem >> 10;
    long k = rem & 1023;
    long t = k >> 7;
    const __half* p = P + (b << 23) + rem;
    float4 s = {0.f, 0.f, 0.f, 0.f};
    #pragma unroll
    for (int h = 0; h < 8; h++) {
        long z = b * 8 + h;
        float c = C[((z * 8 + t) << 10) + q];
        const __half2* p2 = (const __half2*)(p + ((long)h << 20));
        float2 v0 = __half22float2(p2[0]);
        float2 v1 = __half22float2(p2[1]);
        s.x += c * v0.x; s.y += c * v0.y; s.z += c * v1.x; s.w += c * v1.y;
    }
    s.x *= 0.125f; s.y *= 0.125f; s.z *= 0.125f; s.w *= 0.125f;
    *(float4*)(out + i) = s;
}

// ================= launch =================
extern "C" void kernel_launch(void* const* d_in, const int* in_sizes, int n_in,
                              void* d_out, int out_size)
{
    (void)in_sizes; (void)n_in; (void)out_size;
    const float* Zab   = (const float*)d_in[0];
    const float* Za    = (const float*)d_in[1];
    const float* ln_w  = (const float*)d_in[2];
    const float* ln_b  = (const float*)d_in[3];
    const float* in_w  = (const float*)d_in[4];
    const float* in_b  = (const float*)d_in[5];
    const float* out_w = (const float*)d_in[6];
    const float* out_b = (const float*)d_in[7];
    const float* ff_w  = (const float*)d_in[8];
    const float* ff_b  = (const float*)d_in[9];

    float* out_final = (float*)d_out;
    float* out_attnw = (float*)d_out + 8192L * 512;

    bf16 *qin_hi, *qin_lo, *kvin_hi, *kvin_lo, *inw_hi, *inw_lo;
    bf16 *outw_hi, *outw_lo, *ffw_hi, *ffw_lo, *q_hi, *q_lo;
    bf16 *k_hi, *k_lo, *vt_hi, *vt_lo, *ctx_hi, *ctx_lo, *xn_hi, *xn_lo;
    float *v, *x, *xn, *ff, *mb, *cb;
    __half* p;
    float2 *mlb;
    cudaGetSymbolAddress((void**)&qin_hi,  g_qin_hi);
    cudaGetSymbolAddress((void**)&qin_lo,  g_qin_lo);
    cudaGetSymbolAddress((void**)&kvin_hi, g_kvin_hi);
    cudaGetSymbolAddress((void**)&kvin_lo, g_kvin_lo);
    cudaGetSymbolAddress((void**)&inw_hi,  g_inw_hi);
    cudaGetSymbolAddress((void**)&inw_lo,  g_inw_lo);
    cudaGetSymbolAddress((void**)&outw_hi, g_outw_hi);
    cudaGetSymbolAddress((void**)&outw_lo, g_outw_lo);
    cudaGetSymbolAddress((void**)&ffw_hi,  g_ffw_hi);
    cudaGetSymbolAddress((void**)&ffw_lo,  g_ffw_lo);
    cudaGetSymbolAddress((void**)&q_hi,    g_q_hi);
    cudaGetSymbolAddress((void**)&q_lo,    g_q_lo);
    cudaGetSymbolAddress((void**)&k_hi,    g_k_hi);
    cudaGetSymbolAddress((void**)&k_lo,    g_k_lo);
    cudaGetSymbolAddress((void**)&vt_hi,   g_vt_hi);
    cudaGetSymbolAddress((void**)&vt_lo,   g_vt_lo);
    cudaGetSymbolAddress((void**)&ctx_hi,  g_ctx_hi);
    cudaGetSymbolAddress((void**)&ctx_lo,  g_ctx_lo);
    cudaGetSymbolAddress((void**)&xn_hi,   g_xn_hi);
    cudaGetSymbolAddress((void**)&xn_lo,   g_xn_lo);
    cudaGetSymbolAddress((void**)&v,   g_v);
    cudaGetSymbolAddress((void**)&p,   g_p);
    cudaGetSymbolAddress((void**)&x,   g_x);
    cudaGetSymbolAddress((void**)&xn,  g_xn);
    cudaGetSymbolAddress((void**)&ff,  g_ff);
    cudaGetSymbolAddress((void**)&mb,  g_m);
    cudaGetSymbolAddress((void**)&mlb, g_ml);
    cudaGetSymbolAddress((void**)&cb,  g_c);

    const int SMEM_PI  = 2 * (2 * 128 * 80 + 2 * 128 * 80);           // 81920
    const int SMEM_ATT = 6 * 128 * 144 + 4 * 64 * 272 + 2048;         // 182272
    cudaFuncSetAttribute((const void*)proj_qkv,
                         cudaFuncAttributeMaxDynamicSharedMemorySize, SMEM_PI);
    cudaFuncSetAttribute((const void*)gemm_pi,
                         cudaFuncAttributeMaxDynamicSharedMemorySize, SMEM_PI);
    cudaFuncSetAttribute((const void*)attn_flash,
                         cudaFuncAttributeMaxDynamicSharedMemorySize, SMEM_ATT);

    // 1) LN of inputs -> bf16 hi/lo
    ln_kernel2<<<8192, 128>>>(Zab, nullptr, ln_w, ln_b, nullptr, qin_hi, qin_lo);
    ln_kernel2<<<8192, 128>>>(Za,  nullptr, ln_w, ln_b, nullptr, kvin_hi, kvin_lo);

    // 2) split all weights in one launch
    split3_kernel<<<1280, 256>>>(in_w, inw_hi, inw_lo,
                                 out_w, outw_hi, outw_lo,
                                 ff_w, ffw_hi, ffw_lo);

    // 3) fused q/k/v projections (one launch, grid.z selects)
    proj_qkv<<<dim3(4, 64, 3), 256, SMEM_PI>>>(
        qin_hi, qin_lo, kvin_hi, kvin_lo, inw_hi, inw_lo, in_b,
        q_hi, q_lo, k_hi, k_lo, v);

    // 4) V -> transposed hi/lo
    transpose_v_kernel<<<dim3(32, 16, 8), dim3(32, 8)>>>(v, vt_hi, vt_lo);

    // 5) single-pass flash attention -> P'' fp16, m/ml bufs, ctx hi/lo
    attn_flash<<<dim3(8, 1, 64), 256, SMEM_ATT>>>(
        q_hi, q_lo, k_hi, k_lo, vt_hi, vt_lo, p, mb, mlb, ctx_hi, ctx_lo);

    // 6) corr factors, then attn_weights = (1/8) sum_h c * P''
    corr_kernel<<<2048, 256>>>(mb, mlb, cb);
    mean_corr<<<8192, 256>>>(p, cb, out_attnw);

    // 7) x = ctx @ Wo^T + bo + Zab
    gemm_pi<<<dim3(4, 64, 1), 256, SMEM_PI>>>(
        ctx_hi, ctx_lo, outw_hi, outw_lo,
        x, nullptr, nullptr, 1.0f, out_b, Zab);

    // 8) x_n = LN(x)
    ln_kernel2<<<8192, 128>>>(x, nullptr, ln_w, ln_b, xn, xn_hi, xn_lo);

    // 9) ff = x_n @ ff_w^T + ff_b
    gemm_pi<<<dim3(4, 64, 1), 256, SMEM_PI>>>(
        xn_hi, xn_lo, ffw_hi, ffw_lo,
        ff, nullptr, nullptr, 1.0f, ff_b, nullptr);

    // 10) final = LN(x_n + ff) -> d_out
    ln_kernel2<<<8192, 128>>>(xn, ff, ln_w, ln_b, out_final, nullptr, nullptr);
}